// round 1
// baseline (speedup 1.0000x reference)
#include <cuda_runtime.h>

// Problem geometry (fixed by the reference).
#define NCELLS (32 * 256 * 128)      // El*R*Az = 1,048,576 polar cells per batch
#define NVOX   (320 * 320 * 80)      // 8,192,000 voxels per batch
#define BATCH  16
#define CPT    8                     // az-cells per thread (NCELLS % 8 == 0)

// One thread handles 8 consecutive az-cells of one batch. Consecutive az cells
// at small radius frequently map to the SAME voxel -> run-length accumulate in
// a register and emit one atomic per run (cuts atomic traffic exactly where
// L2 per-address serialization would otherwise bite).
__global__ void __launch_bounds__(256)
polar_scatter_kernel(const float* __restrict__ in,
                     const int*   __restrict__ idx,
                     float*       __restrict__ out)
{
    unsigned t    = blockIdx.x * blockDim.x + threadIdx.x;
    unsigned cell = t * CPT;
    if (cell >= NCELLS) return;
    unsigned b = blockIdx.y;

    // Vectorized loads: each thread reads 32B of indices + 32B of values,
    // warp reads 1KB contiguous from each stream.
    const int4*   ip = reinterpret_cast<const int4*>(idx + cell);
    int4 i0 = ip[0];
    int4 i1 = ip[1];
    const float4* vp = reinterpret_cast<const float4*>(
        in + (size_t)b * NCELLS + cell);
    float4 v0 = vp[0];
    float4 v1 = vp[1];

    int   ind[CPT] = { i0.x, i0.y, i0.z, i0.w, i1.x, i1.y, i1.z, i1.w };
    float val[CPT] = { v0.x, v0.y, v0.z, v0.w, v1.x, v1.y, v1.z, v1.w };

    float* ob = out + (size_t)b * NVOX;

    // Run-length fused scatter: one RED.ADD per run of equal voxel index.
    int   cur = ind[0];
    float acc = val[0];
#pragma unroll
    for (int j = 1; j < CPT; j++) {
        if (ind[j] == cur) {
            acc += val[j];
        } else {
            atomicAdd(ob + cur, acc);   // return unused -> REDG
            cur = ind[j];
            acc = val[j];
        }
    }
    atomicAdd(ob + cur, acc);
}

extern "C" void kernel_launch(void* const* d_in, const int* in_sizes, int n_in,
                              void* d_out, int out_size)
{
    const float* polar = (const float*)d_in[0];   // [16,1,32,256,128] f32
    const int*   idx   = (const int*)  d_in[1];   // [1048576] int32 flat voxel idx
    float*       out   = (float*)d_out;           // [16,1,80,320,320] f32

    // Zero the 524MB output (poisoned by harness). Graph-capturable.
    cudaMemsetAsync(d_out, 0, (size_t)out_size * sizeof(float));

    dim3 block(256);
    dim3 grid((NCELLS / CPT + 255) / 256, BATCH);   // (512, 16)
    polar_scatter_kernel<<<grid, block>>>(polar, idx, out);
}